// round 3
// baseline (speedup 1.0000x reference)
#include <cuda_runtime.h>

#define NN 100000
#define EMAX 1600000

// ---------------- scratch (device globals; no allocation allowed) ----------
__device__ float g_ys[(size_t)NN * 128];   // self projection
__device__ float g_yn[(size_t)NN * 128];   // neighbor projection
__device__ float g_h [(size_t)NN * 128];   // layer-1 output
__device__ float g_h2[(size_t)NN * 64];    // layer-2 output
__device__ int   g_deg[NN];
__device__ int   g_off[NN + 1];
__device__ int   g_cur[NN];
__device__ int   g_csr[EMAX];

// ---------------- CSR build -------------------------------------------------
__global__ void k_zero_deg() {
    for (int i = blockIdx.x * blockDim.x + threadIdx.x; i < NN;
         i += gridDim.x * blockDim.x)
        g_deg[i] = 0;
}

__global__ void k_count(const int* __restrict__ dst, int E) {
    int i = blockIdx.x * blockDim.x + threadIdx.x;
    if (i < E) atomicAdd(&g_deg[dst[i]], 1);
}

// single-block exclusive scan over 100001 offsets
__global__ void k_scan() {
    __shared__ int ss[1024];
    int t = threadIdx.x;
    const int CH = (NN + 1023) / 1024;   // 98
    int beg = t * CH;
    if (beg > NN) beg = NN;
    int end = beg + CH;
    if (end > NN) end = NN;
    int s = 0;
    for (int i = beg; i < end; i++) s += g_deg[i];
    ss[t] = s;
    __syncthreads();
    for (int d = 1; d < 1024; d <<= 1) {
        int v = (t >= d) ? ss[t - d] : 0;
        __syncthreads();
        ss[t] += v;
        __syncthreads();
    }
    int run = ss[t] - s;   // exclusive prefix for this chunk
    for (int i = beg; i < end; i++) {
        g_off[i] = run;
        g_cur[i] = run;
        run += g_deg[i];
    }
    if (t == 1023) g_off[NN] = ss[1023];
}

__global__ void k_scatter(const int* __restrict__ src, const int* __restrict__ dst, int E) {
    int i = blockIdx.x * blockDim.x + threadIdx.x;
    if (i < E) {
        int p = atomicAdd(&g_cur[dst[i]], 1);
        g_csr[p] = src[i];
    }
}

// ---------------- fp32 tiled GEMM: C[M,N] = A[M,K] * B[K,N] ----------------
// BM=64, BN=64, BK=16, 256 threads, 4x4 per thread.
__global__ void k_gemm(const float* __restrict__ A, const float* __restrict__ B,
                       float* __restrict__ C, int M, int K, int N)
{
    __shared__ __align__(16) float As[16][64];   // [k][m] (transposed)
    __shared__ __align__(16) float Bs[16][64];   // [k][n]

    int tx = threadIdx.x & 15;        // 0..15 -> 4 cols each
    int ty = threadIdx.x >> 4;        // 0..15 -> 4 rows each
    int bm = blockIdx.x * 64;
    int bn = blockIdx.y * 64;

    // A-tile load mapping: 64 rows x 16 k, one float4 per thread
    int lr = threadIdx.x >> 2;        // 0..63 row
    int lc = (threadIdx.x & 3) * 4;   // 0,4,8,12 k-offset
    // B-tile load mapping: 16 k x 64 n
    int kr = threadIdx.x >> 4;        // 0..15 k
    int kc = (threadIdx.x & 15) * 4;  // n-offset

    float acc[4][4] = {};

    for (int kk = 0; kk < K; kk += 16) {
        float4 av = make_float4(0.f, 0.f, 0.f, 0.f);
        int arow = bm + lr;
        if (arow < M)
            av = *(const float4*)(A + (size_t)arow * K + kk + lc);
        As[lc + 0][lr] = av.x;
        As[lc + 1][lr] = av.y;
        As[lc + 2][lr] = av.z;
        As[lc + 3][lr] = av.w;

        *(float4*)&Bs[kr][kc] = *(const float4*)(B + (size_t)(kk + kr) * N + bn + kc);
        __syncthreads();

#pragma unroll
        for (int k = 0; k < 16; k++) {
            float4 a = *(float4*)&As[k][ty * 4];
            float4 b = *(float4*)&Bs[k][tx * 4];
            acc[0][0] += a.x * b.x; acc[0][1] += a.x * b.y; acc[0][2] += a.x * b.z; acc[0][3] += a.x * b.w;
            acc[1][0] += a.y * b.x; acc[1][1] += a.y * b.y; acc[1][2] += a.y * b.z; acc[1][3] += a.y * b.w;
            acc[2][0] += a.z * b.x; acc[2][1] += a.z * b.y; acc[2][2] += a.z * b.z; acc[2][3] += a.z * b.w;
            acc[3][0] += a.w * b.x; acc[3][1] += a.w * b.y; acc[3][2] += a.w * b.z; acc[3][3] += a.w * b.w;
        }
        __syncthreads();
    }

#pragma unroll
    for (int i = 0; i < 4; i++) {
        int row = bm + ty * 4 + i;
        if (row < M) {
            float4 o = make_float4(acc[i][0], acc[i][1], acc[i][2], acc[i][3]);
            *(float4*)(C + (size_t)row * N + bn + tx * 4) = o;
        }
    }
}

// ---------------- aggregation + epilogue -----------------------------------
// d=128: one warp per node, lane handles one float4 (4 cols).
__global__ void k_agg128_relu(const float* __restrict__ ys, const float* __restrict__ yn,
                              const float* __restrict__ bias, float* __restrict__ out)
{
    int w = (blockIdx.x * blockDim.x + threadIdx.x) >> 5;
    int lane = threadIdx.x & 31;
    if (w >= NN) return;
    int s0 = g_off[w], s1 = g_off[w + 1];
    const float4* yn4 = (const float4*)yn;
    float4 acc = make_float4(0.f, 0.f, 0.f, 0.f);
    for (int e = s0; e < s1; e++) {
        int s = g_csr[e];
        float4 v = yn4[(size_t)s * 32 + lane];
        acc.x += v.x; acc.y += v.y; acc.z += v.z; acc.w += v.w;
    }
    float inv = (s1 > s0) ? 1.f / (float)(s1 - s0) : 0.f;
    float4 sv = ((const float4*)ys)[(size_t)w * 32 + lane];
    float4 bb = ((const float4*)bias)[lane];
    float4 o;
    o.x = fmaxf(sv.x + acc.x * inv + bb.x, 0.f);
    o.y = fmaxf(sv.y + acc.y * inv + bb.y, 0.f);
    o.z = fmaxf(sv.z + acc.z * inv + bb.z, 0.f);
    o.w = fmaxf(sv.w + acc.w * inv + bb.w, 0.f);
    ((float4*)out)[(size_t)w * 32 + lane] = o;
}

// d=64: one warp per node, lane handles one float2 (2 cols).
__global__ void k_agg64_relu(const float* __restrict__ ys, const float* __restrict__ yn,
                             const float* __restrict__ bias, float* __restrict__ out)
{
    int w = (blockIdx.x * blockDim.x + threadIdx.x) >> 5;
    int lane = threadIdx.x & 31;
    if (w >= NN) return;
    int s0 = g_off[w], s1 = g_off[w + 1];
    const float2* yn2 = (const float2*)yn;
    float2 acc = make_float2(0.f, 0.f);
    for (int e = s0; e < s1; e++) {
        int s = g_csr[e];
        float2 v = yn2[(size_t)s * 32 + lane];
        acc.x += v.x; acc.y += v.y;
    }
    float inv = (s1 > s0) ? 1.f / (float)(s1 - s0) : 0.f;
    float2 sv = ((const float2*)ys)[(size_t)w * 32 + lane];
    float2 bb = ((const float2*)bias)[lane];
    float2 o;
    o.x = fmaxf(sv.x + acc.x * inv + bb.x, 0.f);
    o.y = fmaxf(sv.y + acc.y * inv + bb.y, 0.f);
    ((float2*)out)[(size_t)w * 32 + lane] = o;
}

// d=64 + row softmax (final layer)
__global__ void k_agg64_softmax(const float* __restrict__ ys, const float* __restrict__ yn,
                                const float* __restrict__ bias, float* __restrict__ out)
{
    int w = (blockIdx.x * blockDim.x + threadIdx.x) >> 5;
    int lane = threadIdx.x & 31;
    if (w >= NN) return;
    int s0 = g_off[w], s1 = g_off[w + 1];
    const float2* yn2 = (const float2*)yn;
    float2 acc = make_float2(0.f, 0.f);
    for (int e = s0; e < s1; e++) {
        int s = g_csr[e];
        float2 v = yn2[(size_t)s * 32 + lane];
        acc.x += v.x; acc.y += v.y;
    }
    float inv = (s1 > s0) ? 1.f / (float)(s1 - s0) : 0.f;
    float2 sv = ((const float2*)ys)[(size_t)w * 32 + lane];
    float2 bb = ((const float2*)bias)[lane];
    float vx = sv.x + acc.x * inv + bb.x;
    float vy = sv.y + acc.y * inv + bb.y;

    float m = fmaxf(vx, vy);
#pragma unroll
    for (int o = 16; o > 0; o >>= 1)
        m = fmaxf(m, __shfl_xor_sync(0xffffffffu, m, o));
    float ex = __expf(vx - m);
    float ey = __expf(vy - m);
    float s = ex + ey;
#pragma unroll
    for (int o = 16; o > 0; o >>= 1)
        s += __shfl_xor_sync(0xffffffffu, s, o);
    float r = 1.f / s;
    float2 o2 = make_float2(ex * r, ey * r);
    ((float2*)out)[(size_t)w * 32 + lane] = o2;
}

// ---------------- launch ----------------------------------------------------
extern "C" void kernel_launch(void* const* d_in, const int* in_sizes, int n_in,
                              void* d_out, int out_size)
{
    const float* x   = (const float*)d_in[0];
    const int*   src = (const int*)d_in[1];
    const int*   dst = (const int*)d_in[2];
    const float* w1s = (const float*)d_in[3];
    const float* w1n = (const float*)d_in[4];
    const float* b1  = (const float*)d_in[5];
    const float* w2s = (const float*)d_in[6];
    const float* w2n = (const float*)d_in[7];
    const float* b2  = (const float*)d_in[8];
    const float* w3s = (const float*)d_in[9];
    const float* w3n = (const float*)d_in[10];
    const float* b3  = (const float*)d_in[11];
    float* out = (float*)d_out;
    int E = in_sizes[1];
    if (E > EMAX) E = EMAX;

    float *p_ys, *p_yn, *p_h, *p_h2;
    cudaGetSymbolAddress((void**)&p_ys, g_ys);
    cudaGetSymbolAddress((void**)&p_yn, g_yn);
    cudaGetSymbolAddress((void**)&p_h,  g_h);
    cudaGetSymbolAddress((void**)&p_h2, g_h2);

    // CSR build
    k_zero_deg<<<256, 256>>>();
    k_count<<<(E + 255) / 256, 256>>>(dst, E);
    k_scan<<<1, 1024>>>();
    k_scatter<<<(E + 255) / 256, 256>>>(src, dst, E);

    const int MB = (NN + 63) / 64;          // 1563 row blocks
    const int AGG_BLKS = (NN * 32 + 255) / 256;  // 8 warps/block

    // Layer 1: 128 -> 128
    k_gemm<<<dim3(MB, 2), 256>>>(x, w1s, p_ys, NN, 128, 128);
    k_gemm<<<dim3(MB, 2), 256>>>(x, w1n, p_yn, NN, 128, 128);
    k_agg128_relu<<<AGG_BLKS, 256>>>(p_ys, p_yn, b1, p_h);

    // Layer 2: 128 -> 64
    k_gemm<<<dim3(MB, 1), 256>>>(p_h, w2s, p_ys, NN, 128, 64);
    k_gemm<<<dim3(MB, 1), 256>>>(p_h, w2n, p_yn, NN, 128, 64);
    k_agg64_relu<<<AGG_BLKS, 256>>>(p_ys, p_yn, b2, p_h2);

    // Layer 3: 64 -> 64 + softmax
    k_gemm<<<dim3(MB, 1), 256>>>(p_h2, w3s, p_ys, NN, 64, 64);
    k_gemm<<<dim3(MB, 1), 256>>>(p_h2, w3n, p_yn, NN, 64, 64);
    k_agg64_softmax<<<AGG_BLKS, 256>>>(p_ys, p_yn, b3, out);
}

// round 4
// speedup vs baseline: 1.2942x; 1.2942x over previous
#include <cuda_runtime.h>
#include <cuda_bf16.h>

#define NN   100000
#define NPAD 100096            // 782 * 128
#define EMAX 1600000

// ---------------- scratch (device globals; no allocation allowed) ----------
__device__ __nv_bfloat16 g_ahi[(size_t)NPAD * 128];
__device__ __nv_bfloat16 g_alo[(size_t)NPAD * 128];
__device__ float         g_y  [(size_t)NPAD * 256];   // GEMM output [ys | yn]
__device__ __nv_bfloat16 g_bthi[256 * 128];           // packed B^T hi  [2N][K]
__device__ __nv_bfloat16 g_btlo[256 * 128];           // packed B^T lo
__device__ int g_deg[NN];
__device__ int g_off[NN + 1];
__device__ int g_cur[NN];
__device__ int g_csr[EMAX];

// ---------------- CSR build -------------------------------------------------
__global__ void k_zero_deg() {
    for (int i = blockIdx.x * blockDim.x + threadIdx.x; i < NN;
         i += gridDim.x * blockDim.x)
        g_deg[i] = 0;
}

__global__ void k_count(const int* __restrict__ dst, int E) {
    int i = blockIdx.x * blockDim.x + threadIdx.x;
    if (i < E) atomicAdd(&g_deg[dst[i]], 1);
}

__global__ void k_scan() {
    __shared__ int ss[1024];
    int t = threadIdx.x;
    const int CH = (NN + 1023) / 1024;
    int beg = t * CH; if (beg > NN) beg = NN;
    int end = beg + CH; if (end > NN) end = NN;
    int s = 0;
    for (int i = beg; i < end; i++) s += g_deg[i];
    ss[t] = s;
    __syncthreads();
    for (int d = 1; d < 1024; d <<= 1) {
        int v = (t >= d) ? ss[t - d] : 0;
        __syncthreads();
        ss[t] += v;
        __syncthreads();
    }
    int run = ss[t] - s;
    for (int i = beg; i < end; i++) {
        g_off[i] = run;
        g_cur[i] = run;
        run += g_deg[i];
    }
    if (t == 1023) g_off[NN] = ss[1023];
}

__global__ void k_scatter(const int* __restrict__ src, const int* __restrict__ dst, int E) {
    int i = blockIdx.x * blockDim.x + threadIdx.x;
    if (i < E) {
        int p = atomicAdd(&g_cur[dst[i]], 1);
        g_csr[p] = src[i];
    }
}

// ---------------- weight pack: [Ws | Wn] -> B^T bf16 hi/lo -----------------
// ws, wn: [K][N] fp32 row-major. Output g_bt{hi,lo}[n][k], n in [0,2N).
__global__ void k_pack(const float* __restrict__ ws, const float* __restrict__ wn,
                       int K, int N)
{
    int idx = blockIdx.x * blockDim.x + threadIdx.x;
    int total = 2 * N * K;
    if (idx >= total) return;
    int n = idx / K, k = idx - n * K;
    float v = (n < N) ? ws[k * N + n] : wn[k * N + (n - N)];
    __nv_bfloat16 h = __float2bfloat16(v);
    g_bthi[n * K + k] = h;
    g_btlo[n * K + k] = __float2bfloat16(v - __bfloat162float(h));
}

// ---------------- fp32 -> bf16 hi/lo split of the input features -----------
__global__ void k_split4(const float* __restrict__ x, int n4) {
    int i = blockIdx.x * blockDim.x + threadIdx.x;
    if (i >= n4) return;
    float4 v = ((const float4*)x)[i];
    __nv_bfloat16 hx = __float2bfloat16(v.x), hy = __float2bfloat16(v.y);
    __nv_bfloat16 hz = __float2bfloat16(v.z), hw = __float2bfloat16(v.w);
    __nv_bfloat162 h01, h23, l01, l23;
    h01.x = hx; h01.y = hy; h23.x = hz; h23.y = hw;
    l01.x = __float2bfloat16(v.x - __bfloat162float(hx));
    l01.y = __float2bfloat16(v.y - __bfloat162float(hy));
    l23.x = __float2bfloat16(v.z - __bfloat162float(hz));
    l23.y = __float2bfloat16(v.w - __bfloat162float(hw));
    uint2 hp, lp;
    hp.x = *(unsigned*)&h01; hp.y = *(unsigned*)&h23;
    lp.x = *(unsigned*)&l01; lp.y = *(unsigned*)&l23;
    ((uint2*)g_ahi)[i] = hp;
    ((uint2*)g_alo)[i] = lp;
}

// ---------------- tensor-core GEMM (split bf16, 3 products) ----------------
// C[M,2N] = A[M,K] * Bt[2N,K]^T, fp32 accuracy via AhiBhi + AloBhi + AhiBlo.
// Block tile 128x128, 8 warps (4 m-warps x 2 n-warps), warp tile 32x64.
#define MMA16816(d, a0, a1, a2, a3, b0, b1)                                    \
    asm volatile(                                                              \
        "mma.sync.aligned.m16n8k16.row.col.f32.bf16.bf16.f32 "                 \
        "{%0,%1,%2,%3}, {%4,%5,%6,%7}, {%8,%9}, {%0,%1,%2,%3};"               \
        : "+f"(d[0]), "+f"(d[1]), "+f"(d[2]), "+f"(d[3])                       \
        : "r"(a0), "r"(a1), "r"(a2), "r"(a3), "r"(b0), "r"(b1))

#define SROW 24   // smem row stride in bf16 elems (padding kills conflicts)

__global__ __launch_bounds__(256, 2)
void k_gemm_mma(const __nv_bfloat16* __restrict__ Ahi,
                const __nv_bfloat16* __restrict__ Alo,
                float* __restrict__ C, int K, int ldc)
{
    __shared__ __align__(16) __nv_bfloat16 sAh[128 * SROW];
    __shared__ __align__(16) __nv_bfloat16 sAl[128 * SROW];
    __shared__ __align__(16) __nv_bfloat16 sBh[128 * SROW];
    __shared__ __align__(16) __nv_bfloat16 sBl[128 * SROW];

    const int tid = threadIdx.x;
    const int warp = tid >> 5, lane = tid & 31;
    const int g = lane >> 2, t = lane & 3;
    const int wm = warp & 3, wn = warp >> 2;
    const size_t rowbase = (size_t)blockIdx.x * 128;
    const size_t colbase = (size_t)blockIdx.y * 128;

    // gmem tile-load mapping: 128 rows x 16 k, uint4 (8 bf16) per thread
    const int lr = tid >> 1;
    const int lc = (tid & 1) * 8;

    float acc[2][8][4];
#pragma unroll
    for (int i = 0; i < 2; i++)
#pragma unroll
        for (int j = 0; j < 8; j++)
#pragma unroll
            for (int q = 0; q < 4; q++) acc[i][j][q] = 0.f;

    for (int kk = 0; kk < K; kk += 16) {
        uint4 ah = *(const uint4*)(Ahi + (rowbase + lr) * K + kk + lc);
        uint4 al = *(const uint4*)(Alo + (rowbase + lr) * K + kk + lc);
        uint4 bh = *(const uint4*)(g_bthi + (colbase + lr) * K + kk + lc);
        uint4 bl = *(const uint4*)(g_btlo + (colbase + lr) * K + kk + lc);
        __syncthreads();
        *(uint4*)(sAh + lr * SROW + lc) = ah;
        *(uint4*)(sAl + lr * SROW + lc) = al;
        *(uint4*)(sBh + lr * SROW + lc) = bh;
        *(uint4*)(sBl + lr * SROW + lc) = bl;
        __syncthreads();

        unsigned fah[2][4], fal[2][4];
#pragma unroll
        for (int mt = 0; mt < 2; mt++) {
            int r = wm * 32 + mt * 16;
            fah[mt][0] = *(const unsigned*)(sAh + (r + g) * SROW + 2 * t);
            fah[mt][1] = *(const unsigned*)(sAh + (r + g + 8) * SROW + 2 * t);
            fah[mt][2] = *(const unsigned*)(sAh + (r + g) * SROW + 2 * t + 8);
            fah[mt][3] = *(const unsigned*)(sAh + (r + g + 8) * SROW + 2 * t + 8);
            fal[mt][0] = *(const unsigned*)(sAl + (r + g) * SROW + 2 * t);
            fal[mt][1] = *(const unsigned*)(sAl + (r + g + 8) * SROW + 2 * t);
            fal[mt][2] = *(const unsigned*)(sAl + (r + g) * SROW + 2 * t + 8);
            fal[mt][3] = *(const unsigned*)(sAl + (r + g + 8) * SROW + 2 * t + 8);
        }
#pragma unroll
        for (int nt = 0; nt < 8; nt++) {
            int n = wn * 64 + nt * 8 + g;
            unsigned bh0 = *(const unsigned*)(sBh + n * SROW + 2 * t);
            unsigned bh1 = *(const unsigned*)(sBh + n * SROW + 2 * t + 8);
            unsigned bl0 = *(const unsigned*)(sBl + n * SROW + 2 * t);
            unsigned bl1 = *(const unsigned*)(sBl + n * SROW + 2 * t + 8);
#pragma unroll
            for (int mt = 0; mt < 2; mt++) {
                MMA16816(acc[mt][nt], fah[mt][0], fah[mt][1], fah[mt][2], fah[mt][3], bh0, bh1);
                MMA16816(acc[mt][nt], fal[mt][0], fal[mt][1], fal[mt][2], fal[mt][3], bh0, bh1);
                MMA16816(acc[mt][nt], fah[mt][0], fah[mt][1], fah[mt][2], fah[mt][3], bl0, bl1);
            }
        }
    }

#pragma unroll
    for (int mt = 0; mt < 2; mt++) {
#pragma unroll
        for (int nt = 0; nt < 8; nt++) {
            size_t r = rowbase + wm * 32 + mt * 16 + g;
            size_t c = colbase + wn * 64 + nt * 8 + 2 * t;
            float2 v0 = make_float2(acc[mt][nt][0], acc[mt][nt][1]);
            float2 v1 = make_float2(acc[mt][nt][2], acc[mt][nt][3]);
            *(float2*)(C + r * ldc + c) = v0;
            *(float2*)(C + (r + 8) * ldc + c) = v1;
        }
    }
}

// ---------------- aggregation + epilogue -----------------------------------
// y layout: [NPAD][2d] fp32, self = cols [0,d), neigh = cols [d,2d).
// Output: bf16 hi/lo split (feeds next GEMM).

__global__ void k_agg128_relu(const float* __restrict__ y, const float* __restrict__ bias,
                              __nv_bfloat16* __restrict__ ohi, __nv_bfloat16* __restrict__ olo)
{
    int w = (blockIdx.x * blockDim.x + threadIdx.x) >> 5;
    int lane = threadIdx.x & 31;
    if (w >= NN) return;
    int s0 = g_off[w], s1 = g_off[w + 1];
    const float4* y4 = (const float4*)y;       // row stride = 64 float4
    float4 acc = make_float4(0.f, 0.f, 0.f, 0.f);
    for (int e = s0; e < s1; e++) {
        int s = g_csr[e];
        float4 v = y4[(size_t)s * 64 + 32 + lane];
        acc.x += v.x; acc.y += v.y; acc.z += v.z; acc.w += v.w;
    }
    float inv = (s1 > s0) ? 1.f / (float)(s1 - s0) : 0.f;
    float4 sv = y4[(size_t)w * 64 + lane];
    float4 bb = ((const float4*)bias)[lane];
    float4 o;
    o.x = fmaxf(sv.x + acc.x * inv + bb.x, 0.f);
    o.y = fmaxf(sv.y + acc.y * inv + bb.y, 0.f);
    o.z = fmaxf(sv.z + acc.z * inv + bb.z, 0.f);
    o.w = fmaxf(sv.w + acc.w * inv + bb.w, 0.f);

    __nv_bfloat16 hx = __float2bfloat16(o.x), hy = __float2bfloat16(o.y);
    __nv_bfloat16 hz = __float2bfloat16(o.z), hw = __float2bfloat16(o.w);
    __nv_bfloat162 h01, h23, l01, l23;
    h01.x = hx; h01.y = hy; h23.x = hz; h23.y = hw;
    l01.x = __float2bfloat16(o.x - __bfloat162float(hx));
    l01.y = __float2bfloat16(o.y - __bfloat162float(hy));
    l23.x = __float2bfloat16(o.z - __bfloat162float(hz));
    l23.y = __float2bfloat16(o.w - __bfloat162float(hw));
    uint2 hp, lp;
    hp.x = *(unsigned*)&h01; hp.y = *(unsigned*)&h23;
    lp.x = *(unsigned*)&l01; lp.y = *(unsigned*)&l23;
    *(uint2*)(ohi + (size_t)w * 128 + lane * 4) = hp;
    *(uint2*)(olo + (size_t)w * 128 + lane * 4) = lp;
}

__global__ void k_agg64_relu(const float* __restrict__ y, const float* __restrict__ bias,
                             __nv_bfloat16* __restrict__ ohi, __nv_bfloat16* __restrict__ olo)
{
    int w = (blockIdx.x * blockDim.x + threadIdx.x) >> 5;
    int lane = threadIdx.x & 31;
    if (w >= NN) return;
    int s0 = g_off[w], s1 = g_off[w + 1];
    const float2* y2 = (const float2*)y;       // row stride = 64 float2
    float2 acc = make_float2(0.f, 0.f);
    for (int e = s0; e < s1; e++) {
        int s = g_csr[e];
        float2 v = y2[(size_t)s * 64 + 32 + lane];
        acc.x += v.x; acc.y += v.y;
    }
    float inv = (s1 > s0) ? 1.f / (float)(s1 - s0) : 0.f;
    float2 sv = y2[(size_t)w * 64 + lane];
    float2 bb = ((const float2*)bias)[lane];
    float ox = fmaxf(sv.x + acc.x * inv + bb.x, 0.f);
    float oy = fmaxf(sv.y + acc.y * inv + bb.y, 0.f);

    __nv_bfloat16 hx = __float2bfloat16(ox), hy = __float2bfloat16(oy);
    __nv_bfloat162 h01, l01;
    h01.x = hx; h01.y = hy;
    l01.x = __float2bfloat16(ox - __bfloat162float(hx));
    l01.y = __float2bfloat16(oy - __bfloat162float(hy));
    *(unsigned*)(ohi + (size_t)w * 64 + lane * 2) = *(unsigned*)&h01;
    *(unsigned*)(olo + (size_t)w * 64 + lane * 2) = *(unsigned*)&l01;
}

__global__ void k_agg64_softmax(const float* __restrict__ y, const float* __restrict__ bias,
                                float* __restrict__ out)
{
    int w = (blockIdx.x * blockDim.x + threadIdx.x) >> 5;
    int lane = threadIdx.x & 31;
    if (w >= NN) return;
    int s0 = g_off[w], s1 = g_off[w + 1];
    const float2* y2 = (const float2*)y;
    float2 acc = make_float2(0.f, 0.f);
    for (int e = s0; e < s1; e++) {
        int s = g_csr[e];
        float2 v = y2[(size_t)s * 64 + 32 + lane];
        acc.x += v.x; acc.y += v.y;
    }
    float inv = (s1 > s0) ? 1.f / (float)(s1 - s0) : 0.f;
    float2 sv = y2[(size_t)w * 64 + lane];
    float2 bb = ((const float2*)bias)[lane];
    float vx = sv.x + acc.x * inv + bb.x;
    float vy = sv.y + acc.y * inv + bb.y;

    float m = fmaxf(vx, vy);
#pragma unroll
    for (int o = 16; o > 0; o >>= 1)
        m = fmaxf(m, __shfl_xor_sync(0xffffffffu, m, o));
    float ex = __expf(vx - m);
    float ey = __expf(vy - m);
    float s = ex + ey;
#pragma unroll
    for (int o = 16; o > 0; o >>= 1)
        s += __shfl_xor_sync(0xffffffffu, s, o);
    float r = 1.f / s;
    ((float2*)out)[(size_t)w * 32 + lane] = make_float2(ex * r, ey * r);
}

// ---------------- launch ----------------------------------------------------
extern "C" void kernel_launch(void* const* d_in, const int* in_sizes, int n_in,
                              void* d_out, int out_size)
{
    const float* x   = (const float*)d_in[0];
    const int*   src = (const int*)d_in[1];
    const int*   dst = (const int*)d_in[2];
    const float* w1s = (const float*)d_in[3];
    const float* w1n = (const float*)d_in[4];
    const float* b1  = (const float*)d_in[5];
    const float* w2s = (const float*)d_in[6];
    const float* w2n = (const float*)d_in[7];
    const float* b2  = (const float*)d_in[8];
    const float* w3s = (const float*)d_in[9];
    const float* w3n = (const float*)d_in[10];
    const float* b3  = (const float*)d_in[11];
    float* out = (float*)d_out;
    int E = in_sizes[1];
    if (E > EMAX) E = EMAX;

    __nv_bfloat16 *p_ahi, *p_alo;
    float* p_y;
    cudaGetSymbolAddress((void**)&p_ahi, g_ahi);
    cudaGetSymbolAddress((void**)&p_alo, g_alo);
    cudaGetSymbolAddress((void**)&p_y, g_y);

    // CSR build
    k_zero_deg<<<256, 256>>>();
    k_count<<<(E + 255) / 256, 256>>>(dst, E);
    k_scan<<<1, 1024>>>();
    k_scatter<<<(E + 255) / 256, 256>>>(src, dst, E);

    const int MB = NPAD / 128;                    // 782
    const int AGG_BLKS = (NN * 32 + 255) / 256;   // 12500

    // Layer 1: 128 -> 128 (2N = 256)
    k_split4<<<(NN * 128 / 4 + 255) / 256, 256>>>(x, NN * 128 / 4);
    k_pack<<<(2 * 128 * 128 + 255) / 256, 256>>>(w1s, w1n, 128, 128);
    k_gemm_mma<<<dim3(MB, 2), 256>>>(p_ahi, p_alo, p_y, 128, 256);
    k_agg128_relu<<<AGG_BLKS, 256>>>(p_y, b1, p_ahi, p_alo);

    // Layer 2: 128 -> 64 (2N = 128)
    k_pack<<<(2 * 64 * 128 + 255) / 256, 256>>>(w2s, w2n, 128, 64);
    k_gemm_mma<<<dim3(MB, 1), 256>>>(p_ahi, p_alo, p_y, 128, 128);
    k_agg64_relu<<<AGG_BLKS, 256>>>(p_y, b2, p_ahi, p_alo);

    // Layer 3: 64 -> 64 (2N = 128) + softmax
    k_pack<<<(2 * 64 * 64 + 255) / 256, 256>>>(w3s, w3n, 64, 64);
    k_gemm_mma<<<dim3(MB, 1), 256>>>(p_ahi, p_alo, p_y, 64, 128);
    k_agg64_softmax<<<AGG_BLKS, 256>>>(p_y, b3, out);
}

// round 6
// speedup vs baseline: 1.3441x; 1.0386x over previous
#include <cuda_runtime.h>
#include <cuda_bf16.h>

#define NN   100000
#define NPAD 100096            // 782 * 128
#define EMAX 1600000
#define SROW 24                // smem row stride (bf16 elems); 48B -> conflict-free ldmatrix

// ---------------- scratch (device globals; no allocation allowed) ----------
__device__ __nv_bfloat16 g_ahi[(size_t)NPAD * 128];
__device__ __nv_bfloat16 g_alo[(size_t)NPAD * 128];
__device__ float         g_y  [(size_t)NPAD * 256];   // GEMM output [ys | yn]
__device__ __nv_bfloat16 g_bthi[256 * 128];           // packed B^T hi  [2N][K]
__device__ __nv_bfloat16 g_btlo[256 * 128];           // packed B^T lo
__device__ int g_deg[NN];
__device__ int g_off[NN + 1];
__device__ int g_cur[NN];
__device__ int g_csr[EMAX];

// ---------------- CSR build -------------------------------------------------
__global__ void k_zero_deg() {
    for (int i = blockIdx.x * blockDim.x + threadIdx.x; i < NN;
         i += gridDim.x * blockDim.x)
        g_deg[i] = 0;
}

__global__ void k_count(const int* __restrict__ dst, int E) {
    int i0 = (blockIdx.x * blockDim.x + threadIdx.x) * 4;
    if (i0 + 3 < E) {
        int4 d = *(const int4*)(dst + i0);
        atomicAdd(&g_deg[d.x], 1);
        atomicAdd(&g_deg[d.y], 1);
        atomicAdd(&g_deg[d.z], 1);
        atomicAdd(&g_deg[d.w], 1);
    } else {
        for (int j = 0; j < 4; j++) {
            int i = i0 + j;
            if (i < E) atomicAdd(&g_deg[dst[i]], 1);
        }
    }
}

__global__ void k_scan() {
    __shared__ int ss[1024];
    int t = threadIdx.x;
    const int CH = (NN + 1023) / 1024;
    int beg = t * CH; if (beg > NN) beg = NN;
    int end = beg + CH; if (end > NN) end = NN;
    int s = 0;
    for (int i = beg; i < end; i++) s += g_deg[i];
    ss[t] = s;
    __syncthreads();
    for (int d = 1; d < 1024; d <<= 1) {
        int v = (t >= d) ? ss[t - d] : 0;
        __syncthreads();
        ss[t] += v;
        __syncthreads();
    }
    int run = ss[t] - s;
    for (int i = beg; i < end; i++) {
        g_off[i] = run;
        g_cur[i] = run;
        run += g_deg[i];
    }
    if (t == 1023) g_off[NN] = ss[1023];
}

__global__ void k_scatter(const int* __restrict__ src, const int* __restrict__ dst, int E) {
    int i0 = (blockIdx.x * blockDim.x + threadIdx.x) * 4;
    if (i0 + 3 < E) {
        int4 d = *(const int4*)(dst + i0);
        int4 s = *(const int4*)(src + i0);
        int p0 = atomicAdd(&g_cur[d.x], 1);
        int p1 = atomicAdd(&g_cur[d.y], 1);
        int p2 = atomicAdd(&g_cur[d.z], 1);
        int p3 = atomicAdd(&g_cur[d.w], 1);
        g_csr[p0] = s.x; g_csr[p1] = s.y; g_csr[p2] = s.z; g_csr[p3] = s.w;
    } else {
        for (int j = 0; j < 4; j++) {
            int i = i0 + j;
            if (i < E) {
                int p = atomicAdd(&g_cur[dst[i]], 1);
                g_csr[p] = src[i];
            }
        }
    }
}

// ---------------- weight pack: [Ws | Wn] -> B^T bf16 hi/lo -----------------
__global__ void k_pack(const float* __restrict__ ws, const float* __restrict__ wn,
                       int K, int N)
{
    int idx = blockIdx.x * blockDim.x + threadIdx.x;
    int total = 2 * N * K;
    if (idx >= total) return;
    int n = idx / K, k = idx - n * K;
    float v = (n < N) ? ws[k * N + n] : wn[k * N + (n - N)];
    __nv_bfloat16 h = __float2bfloat16(v);
    g_bthi[n * K + k] = h;
    g_btlo[n * K + k] = __float2bfloat16(v - __bfloat162float(h));
}

// ---------------- fp32 -> bf16 hi/lo split of the input features -----------
__global__ void k_split4(const float* __restrict__ x, int n4) {
    int i = blockIdx.x * blockDim.x + threadIdx.x;
    if (i >= n4) return;
    float4 v = ((const float4*)x)[i];
    __nv_bfloat16 hx = __float2bfloat16(v.x), hy = __float2bfloat16(v.y);
    __nv_bfloat16 hz = __float2bfloat16(v.z), hw = __float2bfloat16(v.w);
    __nv_bfloat162 h01, h23, l01, l23;
    h01.x = hx; h01.y = hy; h23.x = hz; h23.y = hw;
    l01.x = __float2bfloat16(v.x - __bfloat162float(hx));
    l01.y = __float2bfloat16(v.y - __bfloat162float(hy));
    l23.x = __float2bfloat16(v.z - __bfloat162float(hz));
    l23.y = __float2bfloat16(v.w - __bfloat162float(hw));
    uint2 hp, lp;
    hp.x = *(unsigned*)&h01; hp.y = *(unsigned*)&h23;
    lp.x = *(unsigned*)&l01; lp.y = *(unsigned*)&l23;
    ((uint2*)g_ahi)[i] = hp;
    ((uint2*)g_alo)[i] = lp;
}

// ---------------- tensor-core GEMM (split bf16, 3 products, pipelined) ------
#define MMA16816(d, a0, a1, a2, a3, b0, b1)                                    \
    asm volatile(                                                              \
        "mma.sync.aligned.m16n8k16.row.col.f32.bf16.bf16.f32 "                 \
        "{%0,%1,%2,%3}, {%4,%5,%6,%7}, {%8,%9}, {%0,%1,%2,%3};"               \
        : "+f"(d[0]), "+f"(d[1]), "+f"(d[2]), "+f"(d[3])                       \
        : "r"(a0), "r"(a1), "r"(a2), "r"(a3), "r"(b0), "r"(b1))

__device__ __forceinline__ void ldsm4(unsigned& r0, unsigned& r1,
                                      unsigned& r2, unsigned& r3, unsigned addr) {
    asm volatile("ldmatrix.sync.aligned.m8n8.x4.shared.b16 {%0,%1,%2,%3}, [%4];"
                 : "=r"(r0), "=r"(r1), "=r"(r2), "=r"(r3) : "r"(addr));
}

__device__ __forceinline__ void cpasync16(unsigned dst, const void* src) {
    asm volatile("cp.async.ca.shared.global [%0], [%1], 16;" :: "r"(dst), "l"(src));
}

// C[M,2N] = A[M,K] * Bt[2N,K]^T. Block tile 128x128, 8 warps (4m x 2n),
// warp tile 32x64. 2-stage cp.async double buffer, ldmatrix fragment loads.
__global__ __launch_bounds__(256, 2)
void k_gemm_mma(const __nv_bfloat16* __restrict__ Ahi,
                const __nv_bfloat16* __restrict__ Alo,
                float* __restrict__ C, int K, int ldc)
{
    __shared__ __align__(16) __nv_bfloat16 sm[2 * 4 * 128 * SROW];
    const int TILE = 128 * SROW;                // elems per tile

    const int tid = threadIdx.x;
    const int warp = tid >> 5, lane = tid & 31;
    const int wm = warp & 3, wn = warp >> 2;
    const size_t rowbase = (size_t)blockIdx.x * 128;
    const size_t colbase = (size_t)blockIdx.y * 128;

    // cp.async mapping: 128 rows x 16 k per tile, one 16B op per thread per tile
    const int lr = tid >> 1;
    const int lc = (tid & 1) * 8;

    const unsigned sbase = (unsigned)__cvta_generic_to_shared(sm);
    const unsigned sdst = sbase + (unsigned)(lr * SROW + lc) * 2;

    const __nv_bfloat16* gsrc0 = Ahi    + (rowbase + lr) * K + lc;
    const __nv_bfloat16* gsrc1 = Alo    + (rowbase + lr) * K + lc;
    const __nv_bfloat16* gsrc2 = g_bthi + (colbase + lr) * K + lc;
    const __nv_bfloat16* gsrc3 = g_btlo + (colbase + lr) * K + lc;

    float acc[2][8][4];
#pragma unroll
    for (int i = 0; i < 2; i++)
#pragma unroll
        for (int j = 0; j < 8; j++)
#pragma unroll
            for (int q = 0; q < 4; q++) acc[i][j][q] = 0.f;

    const int KT = K >> 4;

    // prologue: stage 0
    cpasync16(sdst + 0 * TILE * 2, gsrc0);
    cpasync16(sdst + 1 * TILE * 2, gsrc1);
    cpasync16(sdst + 2 * TILE * 2, gsrc2);
    cpasync16(sdst + 3 * TILE * 2, gsrc3);
    asm volatile("cp.async.commit_group;");

    // fragment address pieces (per-lane, constant across iters)
    const int a_row = (lane & 15);            // row within 16-row tile
    const int a_kh  = (lane >> 4) * 8;        // k half offset (elems)
    const int b_n   = (lane & 7) + (lane >> 4) * 8;
    const int b_kh  = ((lane >> 3) & 1) * 8;

    for (int it = 0; it < KT; it++) {
        if (it + 1 < KT) {
            unsigned d = sdst + (unsigned)(((it + 1) & 1) * 4) * TILE * 2;
            int ko = (it + 1) * 16;
            cpasync16(d + 0 * TILE * 2, gsrc0 + ko);
            cpasync16(d + 1 * TILE * 2, gsrc1 + ko);
            cpasync16(d + 2 * TILE * 2, gsrc2 + ko);
            cpasync16(d + 3 * TILE * 2, gsrc3 + ko);
            asm volatile("cp.async.commit_group;");
            asm volatile("cp.async.wait_group 1;");
        } else {
            asm volatile("cp.async.wait_group 0;");
        }
        __syncthreads();

        const unsigned ub = sbase + (unsigned)((it & 1) * 4) * TILE * 2;
        const unsigned uAh = ub + 0 * TILE * 2;
        const unsigned uAl = ub + 1 * TILE * 2;
        const unsigned uBh = ub + 2 * TILE * 2;
        const unsigned uBl = ub + 3 * TILE * 2;

        // A fragments: 2 m-tiles x (hi, lo)
        unsigned fah[2][4], fal[2][4];
#pragma unroll
        for (int mt = 0; mt < 2; mt++) {
            int r0 = wm * 32 + mt * 16;
            unsigned addr = (unsigned)((r0 + a_row) * SROW + a_kh) * 2;
            ldsm4(fah[mt][0], fah[mt][1], fah[mt][2], fah[mt][3], uAh + addr);
            ldsm4(fal[mt][0], fal[mt][1], fal[mt][2], fal[mt][3], uAl + addr);
        }

        // B: 4 n-pairs, each x4 gives frags for two n-tiles (hi and lo)
#pragma unroll
        for (int np = 0; np < 4; np++) {
            int n0 = wn * 64 + np * 16;
            unsigned addr = (unsigned)((n0 + b_n) * SROW + b_kh) * 2;
            unsigned bh0, bh1, bh2, bh3, bl0, bl1, bl2, bl3;
            ldsm4(bh0, bh1, bh2, bh3, uBh + addr);
            ldsm4(bl0, bl1, bl2, bl3, uBl + addr);
#pragma unroll
            for (int mt = 0; mt < 2; mt++) {
                MMA16816(acc[mt][2 * np],     fah[mt][0], fah[mt][1], fah[mt][2], fah[mt][3], bh0, bh1);
                MMA16816(acc[mt][2 * np],     fal[mt][0], fal[mt][1], fal[mt][2], fal[mt][3], bh0, bh1);
                MMA16816(acc[mt][2 * np],     fah[mt][0], fah[mt][1], fah[mt][2], fah[mt][3], bl0, bl1);
                MMA16816(acc[mt][2 * np + 1], fah[mt][0], fah[mt][1], fah[mt][2], fah[mt][3], bh2, bh3);
                MMA16816(acc[mt][2 * np + 1], fal[mt][0], fal[mt][1], fal[mt][2], fal[mt][3], bh2, bh3);
                MMA16816(acc[mt][2 * np + 1], fah[mt][0], fah[mt][1], fah[mt][2], fah[mt][3], bl2, bl3);
            }
        }
        __syncthreads();
    }

    const int g = lane >> 2, t = lane & 3;
#pragma unroll
    for (int mt = 0; mt < 2; mt++) {
#pragma unroll
        for (int nt = 0; nt < 8; nt++) {
            size_t r = rowbase + wm * 32 + mt * 16 + g;
            size_t c = colbase + wn * 64 + nt * 8 + 2 * t;
            *(float2*)(C + r * ldc + c)       = make_float2(acc[mt][nt][0], acc[mt][nt][1]);
            *(float2*)(C + (r + 8) * ldc + c) = make_float2(acc[mt][nt][2], acc[mt][nt][3]);
        }
    }
}

// ---------------- aggregation + epilogue -----------------------------------
__global__ void k_agg128_relu(const float* __restrict__ y, const float* __restrict__ bias,
                              __nv_bfloat16* __restrict__ ohi, __nv_bfloat16* __restrict__ olo)
{
    int w = (blockIdx.x * blockDim.x + threadIdx.x) >> 5;
    int lane = threadIdx.x & 31;
    if (w >= NN) return;
    int s0 = g_off[w], s1 = g_off[w + 1];
    const float4* y4 = (const float4*)y;       // row stride = 64 float4
    float4 acc = make_float4(0.f, 0.f, 0.f, 0.f);
    for (int e = s0; e < s1; e++) {
        int s = g_csr[e];
        float4 v = y4[(size_t)s * 64 + 32 + lane];
        acc.x += v.x; acc.y += v.y; acc.z += v.z; acc.w += v.w;
    }
    float inv = (s1 > s0) ? 1.f / (float)(s1 - s0) : 0.f;
    float4 sv = y4[(size_t)w * 64 + lane];
    float4 bb = ((const float4*)bias)[lane];
    float4 o;
    o.x = fmaxf(sv.x + acc.x * inv + bb.x, 0.f);
    o.y = fmaxf(sv.y + acc.y * inv + bb.y, 0.f);
    o.z = fmaxf(sv.z + acc.z * inv + bb.z, 0.f);
    o.w = fmaxf(sv.w + acc.w * inv + bb.w, 0.f);

    __nv_bfloat16 hx = __float2bfloat16(o.x), hy = __float2bfloat16(o.y);
    __nv_bfloat16 hz = __float2bfloat16(o.z), hw = __float2bfloat16(o.w);
    __nv_bfloat162 h01, h23, l01, l23;
    h01.x = hx; h01.y = hy; h23.x = hz; h23.y = hw;
    l01.x = __float2bfloat16(o.x - __bfloat162float(hx));
    l01.y = __float2bfloat16(o.y - __bfloat162float(hy));
    l23.x = __float2bfloat16(o.z - __bfloat162float(hz));
    l23.y = __float2bfloat16(o.w - __bfloat162float(hw));
    uint2 hp, lp;
    hp.x = *(unsigned*)&h01; hp.y = *(unsigned*)&h23;
    lp.x = *(unsigned*)&l01; lp.y = *(unsigned*)&l23;
    *(uint2*)(ohi + (size_t)w * 128 + lane * 4) = hp;
    *(uint2*)(olo + (size_t)w * 128 + lane * 4) = lp;
}

__global__ void k_agg64_relu(const float* __restrict__ y, const float* __restrict__ bias,
                             __nv_bfloat16* __restrict__ ohi, __nv_bfloat16* __restrict__ olo)
{
    int w = (blockIdx.x * blockDim.x + threadIdx.x) >> 5;
    int lane = threadIdx.x & 31;
    if (w >= NN) return;
    int s0 = g_off[w], s1 = g_off[w + 1];
    const float2* y2 = (const float2*)y;       // row stride = 64 float2
    float2 acc = make_float2(0.f, 0.f);
    for (int e = s0; e < s1; e++) {
        int s = g_csr[e];
        float2 v = y2[(size_t)s * 64 + 32 + lane];
        acc.x += v.x; acc.y += v.y;
    }
    float inv = (s1 > s0) ? 1.f / (float)(s1 - s0) : 0.f;
    float2 sv = y2[(size_t)w * 64 + lane];
    float2 bb = ((const float2*)bias)[lane];
    float ox = fmaxf(sv.x + acc.x * inv + bb.x, 0.f);
    float oy = fmaxf(sv.y + acc.y * inv + bb.y, 0.f);

    __nv_bfloat16 hx = __float2bfloat16(ox), hy = __float2bfloat16(oy);
    __nv_bfloat162 h01, l01;
    h01.x = hx; h01.y = hy;
    l01.x = __float2bfloat16(ox - __bfloat162float(hx));
    l01.y = __float2bfloat16(oy - __bfloat162float(hy));
    *(unsigned*)(ohi + (size_t)w * 64 + lane * 2) = *(unsigned*)&h01;
    *(unsigned*)(olo + (size_t)w * 64 + lane * 2) = *(unsigned*)&l01;
}

__global__ void k_agg64_softmax(const float* __restrict__ y, const float* __restrict__ bias,
                                float* __restrict__ out)
{
    int w = (blockIdx.x * blockDim.x + threadIdx.x) >> 5;
    int lane = threadIdx.x & 31;
    if (w >= NN) return;
    int s0 = g_off[w], s1 = g_off[w + 1];
    const float2* y2 = (const float2*)y;
    float2 acc = make_float2(0.f, 0.f);
    for (int e = s0; e < s1; e++) {
        int s = g_csr[e];
        float2 v = y2[(size_t)s * 64 + 32 + lane];
        acc.x += v.x; acc.y += v.y;
    }
    float inv = (s1 > s0) ? 1.f / (float)(s1 - s0) : 0.f;
    float2 sv = y2[(size_t)w * 64 + lane];
    float2 bb = ((const float2*)bias)[lane];
    float vx = sv.x + acc.x * inv + bb.x;
    float vy = sv.y + acc.y * inv + bb.y;

    float m = fmaxf(vx, vy);
#pragma unroll
    for (int o = 16; o > 0; o >>= 1)
        m = fmaxf(m, __shfl_xor_sync(0xffffffffu, m, o));
    float ex = __expf(vx - m);
    float ey = __expf(vy - m);
    float s = ex + ey;
#pragma unroll
    for (int o = 16; o > 0; o >>= 1)
        s += __shfl_xor_sync(0xffffffffu, s, o);
    float r = 1.f / s;
    ((float2*)out)[(size_t)w * 32 + lane] = make_float2(ex * r, ey * r);
}

// ---------------- launch ----------------------------------------------------
extern "C" void kernel_launch(void* const* d_in, const int* in_sizes, int n_in,
                              void* d_out, int out_size)
{
    const float* x   = (const float*)d_in[0];
    const int*   src = (const int*)d_in[1];
    const int*   dst = (const int*)d_in[2];
    const float* w1s = (const float*)d_in[3];
    const float* w1n = (const float*)d_in[4];
    const float* b1  = (const float*)d_in[5];
    const float* w2s = (const float*)d_in[6];
    const float* w2n = (const float*)d_in[7];
    const float* b2  = (const float*)d_in[8];
    const float* w3s = (const float*)d_in[9];
    const float* w3n = (const float*)d_in[10];
    const float* b3  = (const float*)d_in[11];
    float* out = (float*)d_out;
    int E = in_sizes[1];
    if (E > EMAX) E = EMAX;

    __nv_bfloat16 *p_ahi, *p_alo;
    float* p_y;
    cudaGetSymbolAddress((void**)&p_ahi, g_ahi);
    cudaGetSymbolAddress((void**)&p_alo, g_alo);
    cudaGetSymbolAddress((void**)&p_y, g_y);

    const int MB = NPAD / 128;                    // 782
    const int AGG_BLKS = (NN * 32 + 255) / 256;   // 12500
    const int E4 = (E + 3) / 4;

    // Layer 1 prep (GEMM placed early so the ncu -s window catches it)
    k_split4<<<(NN * 128 / 4 + 255) / 256, 256>>>(x, NN * 128 / 4);          // 0
    k_pack<<<(2 * 128 * 128 + 255) / 256, 256>>>(w1s, w1n, 128, 128);        // 1
    k_zero_deg<<<256, 256>>>();                                              // 2
    k_gemm_mma<<<dim3(MB, 2), 256>>>(p_ahi, p_alo, p_y, 128, 256);           // 3 (profiled)
    k_count<<<(E4 + 255) / 256, 256>>>(dst, E);                              // 4
    k_scan<<<1, 1024>>>();                                                   // 5
    k_scatter<<<(E4 + 255) / 256, 256>>>(src, dst, E);                       // 6
    k_agg128_relu<<<AGG_BLKS, 256>>>(p_y, b1, p_ahi, p_alo);                 // 7

    // Layer 2: 128 -> 64 (2N = 128)
    k_pack<<<(2 * 64 * 128 + 255) / 256, 256>>>(w2s, w2n, 128, 64);
    k_gemm_mma<<<dim3(MB, 1), 256>>>(p_ahi, p_alo, p_y, 128, 128);
    k_agg64_relu<<<AGG_BLKS, 256>>>(p_y, b2, p_ahi, p_alo);

    // Layer 3: 64 -> 64 (2N = 128) + softmax
    k_pack<<<(2 * 64 * 64 + 255) / 256, 256>>>(w3s, w3n, 64, 64);
    k_gemm_mma<<<dim3(MB, 1), 256>>>(p_ahi, p_alo, p_y, 64, 128);
    k_agg64_softmax<<<AGG_BLKS, 256>>>(p_y, b3, out);
}